// round 3
// baseline (speedup 1.0000x reference)
#include <cuda_runtime.h>

// Guided filter, radius=3, fully fused per 32x32 output tile.
// B=8, H=W=1024, p has 3 channels. Output float32.

#define RAD 3
#define TILE 32
#define MREG 38          // TILE + 2*RAD  (a/b region)
#define SREG 44          // TILE + 4*RAD  (raw load region)
#define SPITCH 45        // odd pitch for raw buffers
#define MPITCH 39        // odd pitch for mean/ab/ht buffers
#define TPITCH 33        // odd pitch for stage-2 temp
#define NTHREADS 256
#define HDIM 1024
#define WDIM 1024
#define HW (HDIM * WDIM)
#define INV49 (1.0f / 49.0f)
#define EPS_GF 1e-6f

// smem layout (float offsets)
#define OFF_SI   0                      // SREG x SPITCH = 1980
#define OFF_SP   1980                   // SREG x SPITCH = 1980
#define OFF_HT0  3960                   // SREG x MPITCH = 1716
#define OFF_HT1  5676                   // SREG x MPITCH = 1716
#define OFF_MI   7392                   // MREG x MPITCH = 1482
#define OFF_RV   8874                   // MREG x MPITCH = 1482
#define OFF_AA   10356                  // MREG x MPITCH = 1482
#define OFF_AB   11838                  // MREG x MPITCH = 1482
#define OFF_THA  13320                  // MREG x TPITCH = 1254
#define OFF_THB  14574                  // MREG x TPITCH = 1254
#define SMEM_FLOATS 15828
#define SMEM_BYTES (SMEM_FLOATS * 4)

__global__ void __launch_bounds__(NTHREADS)
guided_filter_kernel(const float* __restrict__ gI,
                     const float* __restrict__ gP,
                     float* __restrict__ gOut) {
    extern __shared__ float sm[];
    float* sI  = sm + OFF_SI;
    float* sP  = sm + OFF_SP;
    float* ht0 = sm + OFF_HT0;
    float* ht1 = sm + OFF_HT1;
    float* mI  = sm + OFF_MI;
    float* rv  = sm + OFF_RV;
    float* aA  = sm + OFF_AA;
    float* aB  = sm + OFF_AB;
    float* thA = sm + OFF_THA;
    float* thB = sm + OFF_THB;

    const int tid = threadIdx.x;
    const int bx = blockIdx.x, by = blockIdx.y, bz = blockIdx.z;
    const int gx0 = bx * TILE - 2 * RAD;
    const int gy0 = by * TILE - 2 * RAD;

    // ---------- load I region (zero-padded) ----------
    {
        const float* Ib = gI + (size_t)bz * HW;
        for (int i = tid; i < SREG * SREG; i += NTHREADS) {
            int y = i / SREG, x = i - y * SREG;
            int gy = gy0 + y, gx = gx0 + x;
            float v = 0.0f;
            if ((unsigned)gy < (unsigned)HDIM && (unsigned)gx < (unsigned)WDIM)
                v = Ib[(size_t)gy * WDIM + gx];
            sI[y * SPITCH + x] = v;
        }
    }
    __syncthreads();

    // ---------- stage 1a: h-pass of {I, I*I} ----------
    // items: 10 x-chunks (4 outputs each) * SREG rows; lanes vary over y -> pitch-45 stride
    for (int i = tid; i < 10 * SREG; i += NTHREADS) {
        int c = i / SREG, y = i - c * SREG;
        int x0 = 4 * c;
        float vi[10];
#pragma unroll
        for (int d = 0; d < 10; d++) {
            int x = x0 + d;
            vi[d] = (x < SREG) ? sI[y * SPITCH + x] : 0.0f;
        }
        float s0 = 0.0f, s1 = 0.0f;
#pragma unroll
        for (int d = 0; d < 7; d++) { s0 += vi[d]; s1 += vi[d] * vi[d]; }
#pragma unroll
        for (int k = 0; k < 4; k++) {
            int x = x0 + k;
            if (x < MREG) { ht0[y * MPITCH + x] = s0; ht1[y * MPITCH + x] = s1; }
            if (k < 3) {
                s0 += vi[k + 7] - vi[k];
                s1 += vi[k + 7] * vi[k + 7] - vi[k] * vi[k];
            }
        }
    }
    __syncthreads();

    // ---------- stage 1a: v-pass -> mean_I, 1/(var+eps) ----------
    for (int i = tid; i < 10 * MREG; i += NTHREADS) {
        int c = i / MREG, ax = i - c * MREG;
        int y0 = 4 * c;
        float v0[10], v1[10];
#pragma unroll
        for (int d = 0; d < 10; d++) {
            int y = y0 + d;
            bool ok = (y < SREG);
            v0[d] = ok ? ht0[y * MPITCH + ax] : 0.0f;
            v1[d] = ok ? ht1[y * MPITCH + ax] : 0.0f;
        }
        float s0 = 0.0f, s1 = 0.0f;
#pragma unroll
        for (int d = 0; d < 7; d++) { s0 += v0[d]; s1 += v1[d]; }
#pragma unroll
        for (int k = 0; k < 4; k++) {
            int ay = y0 + k;
            if (ay < MREG) {
                float mi = s0 * INV49;
                float var = s1 * INV49 - mi * mi;
                mI[ay * MPITCH + ax] = mi;
                rv[ay * MPITCH + ax] = 1.0f / (var + EPS_GF);
            }
            if (k < 3) { s0 += v0[k + 7] - v0[k]; s1 += v1[k + 7] - v1[k]; }
        }
    }
    __syncthreads();

    // ---------- per-channel ----------
    for (int ch = 0; ch < 3; ch++) {
        // load p channel region
        {
            const float* Pb = gP + ((size_t)bz * 3 + ch) * HW;
            for (int i = tid; i < SREG * SREG; i += NTHREADS) {
                int y = i / SREG, x = i - y * SREG;
                int gy = gy0 + y, gx = gx0 + x;
                float v = 0.0f;
                if ((unsigned)gy < (unsigned)HDIM && (unsigned)gx < (unsigned)WDIM)
                    v = Pb[(size_t)gy * WDIM + gx];
                sP[y * SPITCH + x] = v;
            }
        }
        __syncthreads();

        // h-pass of {p, I*p}
        for (int i = tid; i < 10 * SREG; i += NTHREADS) {
            int c = i / SREG, y = i - c * SREG;
            int x0 = 4 * c;
            float vi[10], vp[10];
#pragma unroll
            for (int d = 0; d < 10; d++) {
                int x = x0 + d;
                bool ok = (x < SREG);
                vi[d] = ok ? sI[y * SPITCH + x] : 0.0f;
                vp[d] = ok ? sP[y * SPITCH + x] : 0.0f;
            }
            float s0 = 0.0f, s1 = 0.0f;
#pragma unroll
            for (int d = 0; d < 7; d++) { s0 += vp[d]; s1 += vi[d] * vp[d]; }
#pragma unroll
            for (int k = 0; k < 4; k++) {
                int x = x0 + k;
                if (x < MREG) { ht0[y * MPITCH + x] = s0; ht1[y * MPITCH + x] = s1; }
                if (k < 3) {
                    s0 += vp[k + 7] - vp[k];
                    s1 += vi[k + 7] * vp[k + 7] - vi[k] * vp[k];
                }
            }
        }
        __syncthreads();

        // v-pass -> mean_p, mean_Ip -> a, b (zeroed outside image, matching
        // reference zero-padding of a/b before the second box filter)
        for (int i = tid; i < 10 * MREG; i += NTHREADS) {
            int c = i / MREG, ax = i - c * MREG;
            int y0 = 4 * c;
            int gxa = bx * TILE + ax - RAD;
            bool xok = ((unsigned)gxa < (unsigned)WDIM);
            float v0[10], v1[10];
#pragma unroll
            for (int d = 0; d < 10; d++) {
                int y = y0 + d;
                bool ok = (y < SREG);
                v0[d] = ok ? ht0[y * MPITCH + ax] : 0.0f;
                v1[d] = ok ? ht1[y * MPITCH + ax] : 0.0f;
            }
            float s0 = 0.0f, s1 = 0.0f;
#pragma unroll
            for (int d = 0; d < 7; d++) { s0 += v0[d]; s1 += v1[d]; }
#pragma unroll
            for (int k = 0; k < 4; k++) {
                int ay = y0 + k;
                if (ay < MREG) {
                    int gya = by * TILE + ay - RAD;
                    float aV = 0.0f, bV = 0.0f;
                    if (xok && (unsigned)gya < (unsigned)HDIM) {
                        float mp  = s0 * INV49;
                        float mip = s1 * INV49;
                        int idx = ay * MPITCH + ax;
                        float mi = mI[idx];
                        float r  = rv[idx];
                        aV = (mip - mi * mp) * r;
                        bV = mp - aV * mi;
                    }
                    aA[ay * MPITCH + ax] = aV;
                    aB[ay * MPITCH + ax] = bV;
                }
                if (k < 3) { s0 += v0[k + 7] - v0[k]; s1 += v1[k + 7] - v1[k]; }
            }
        }
        __syncthreads();

        // stage 2 h-pass of {a, b}: 8 x-chunks * MREG rows
        for (int i = tid; i < 8 * MREG; i += NTHREADS) {
            int c = i / MREG, ay = i - c * MREG;
            int x0 = 4 * c;
            float va[10], vb[10];
#pragma unroll
            for (int d = 0; d < 10; d++) {
                int x = x0 + d;   // x0+9 <= 37 < MREG: always valid
                va[d] = aA[ay * MPITCH + x];
                vb[d] = aB[ay * MPITCH + x];
            }
            float s0 = 0.0f, s1 = 0.0f;
#pragma unroll
            for (int d = 0; d < 7; d++) { s0 += va[d]; s1 += vb[d]; }
#pragma unroll
            for (int k = 0; k < 4; k++) {
                int x = x0 + k;   // < 32 always
                thA[ay * TPITCH + x] = s0;
                thB[ay * TPITCH + x] = s1;
                if (k < 3) { s0 += va[k + 7] - va[k]; s1 += vb[k + 7] - vb[k]; }
            }
        }
        __syncthreads();

        // stage 2 v-pass + combine + store (exactly 256 items)
        {
            int ox = tid & 31;
            int cy = tid >> 5;
            int y0 = 4 * cy;
            float va[10], vb[10];
#pragma unroll
            for (int d = 0; d < 10; d++) {   // y0+9 <= 37 < MREG: valid
                va[d] = thA[(y0 + d) * TPITCH + ox];
                vb[d] = thB[(y0 + d) * TPITCH + ox];
            }
            float s0 = 0.0f, s1 = 0.0f;
#pragma unroll
            for (int d = 0; d < 7; d++) { s0 += va[d]; s1 += vb[d]; }
            float* Ob = gOut + ((size_t)bz * 3 + ch) * HW;
#pragma unroll
            for (int k = 0; k < 4; k++) {
                int oy = y0 + k;
                float ma = s0 * INV49;
                float mb = s1 * INV49;
                float Ic = sI[(oy + 2 * RAD) * SPITCH + (ox + 2 * RAD)];
                float q = ma * Ic + mb;
                q = fminf(fmaxf(q, 0.0f), 1.0f);
                Ob[(size_t)(by * TILE + oy) * WDIM + (bx * TILE + ox)] = q;
                if (k < 3) { s0 += va[k + 7] - va[k]; s1 += vb[k + 7] - vb[k]; }
            }
        }
        __syncthreads();
    }
}

extern "C" void kernel_launch(void* const* d_in, const int* in_sizes, int n_in,
                              void* d_out, int out_size) {
    // metadata order: I (8*1*1024*1024), p (8*3*1024*1024), radius (ignored, =3)
    const float* I = (const float*)d_in[0];
    const float* p = (const float*)d_in[1];
    // defensive: I is the smaller tensor
    if (n_in >= 2 && in_sizes[0] > in_sizes[1]) {
        const float* t = I; I = p; p = t;
    }
    float* out = (float*)d_out;

    cudaFuncSetAttribute(guided_filter_kernel,
                         cudaFuncAttributeMaxDynamicSharedMemorySize, SMEM_BYTES);
    dim3 grid(WDIM / TILE, HDIM / TILE, 8);
    guided_filter_kernel<<<grid, NTHREADS, SMEM_BYTES>>>(I, p, out);
}

// round 4
// speedup vs baseline: 1.8489x; 1.8489x over previous
#include <cuda_runtime.h>

// Guided filter r=3, streaming register-sliding-window design.
// Tile: 32 wide x 64 tall. B=8, H=W=1024, 3 p-channels. fp32.

#define NT 256
#define WD 1024
#define HD 1024
#define HW (1024 * 1024)
#define INV49 (1.0f / 49.0f)
#define EPS_GF 1e-6f

#define VP 45            // v-plane pitch (44 cols used), odd
#define HP 33            // hs-plane pitch (32 cols used), odd
#define VROWS 70         // ab rows per tile (64 + 6)

// smem float offsets
#define OFF_VI  0
#define OFF_VII (VROWS * VP)            // 3150
#define OFF_VPP (2 * VROWS * VP)        // 6300
#define OFF_VIP (3 * VROWS * VP)        // 9450
#define OFF_HSA (4 * VROWS * VP)        // 12600
#define OFF_HSB (4 * VROWS * VP + VROWS * HP)
#define SMEM_FL (4 * VROWS * VP + 2 * VROWS * HP)   // 17220
#define SMEM_BYTES (SMEM_FL * 4)                    // 68880

__global__ void __launch_bounds__(NT, 3)
gf_kernel(const float* __restrict__ gI,
          const float* __restrict__ gP,
          float* __restrict__ gOut) {
    extern __shared__ float sm[];
    float* vI  = sm + OFF_VI;
    float* vII = sm + OFF_VII;
    float* vp  = sm + OFF_VPP;
    float* vIp = sm + OFF_VIP;
    float* hsA = sm + OFF_HSA;
    float* hsB = sm + OFF_HSB;

    const int tid = threadIdx.x;
    const int bx = blockIdx.x, by = blockIdx.y, bz = blockIdx.z;
    const int x0 = bx * 32, y0 = by * 64;
    const float* Ib = gI + (size_t)bz * HW;

    // ---------------- V1-I: vertical 7-sums of I, I*I (once per tile) ----
    // thread = (v-column vx in [0,44), segment in [0,5)); 14 ab-rows/segment
    if (tid < 220) {
        int seg = tid / 44;
        int vx  = tid - seg * 44;
        int gxv = x0 + vx - 6;
        bool xok = (unsigned)gxv < (unsigned)WD;
        int gyr0 = y0 + seg * 14 - 6;
        int ya0 = seg * 14;
        float hi[7];
        float sI = 0.f, sII = 0.f;
#pragma unroll
        for (int t = 0; t < 7; t++) hi[t] = 0.f;
#pragma unroll
        for (int t = 0; t < 20; t++) {
            int gyr = gyr0 + t;
            float iv = 0.f;
            if (xok && (unsigned)gyr < (unsigned)HD)
                iv = Ib[(size_t)gyr * WD + gxv];
            float oi = hi[t % 7];
            sI  += iv - oi;
            sII += iv * iv - oi * oi;
            hi[t % 7] = iv;
            if (t >= 6) {
                int idx = (ya0 + t - 6) * VP + vx;
                vI[idx]  = sI;
                vII[idx] = sII;
            }
        }
    }

    for (int ch = 0; ch < 3; ch++) {
        const float* Pb = gP + ((size_t)bz * 3 + ch) * HW;

        // ---------------- V1-p: vertical 7-sums of p, I*p -----------------
        if (tid < 220) {
            int seg = tid / 44;
            int vx  = tid - seg * 44;
            int gxv = x0 + vx - 6;
            bool xok = (unsigned)gxv < (unsigned)WD;
            int gyr0 = y0 + seg * 14 - 6;
            int ya0 = seg * 14;
            float hi[7], hq[7];
            float sp = 0.f, sIp = 0.f;
#pragma unroll
            for (int t = 0; t < 7; t++) { hi[t] = 0.f; hq[t] = 0.f; }
#pragma unroll
            for (int t = 0; t < 20; t++) {
                int gyr = gyr0 + t;
                float iv = 0.f, pv = 0.f;
                if (xok && (unsigned)gyr < (unsigned)HD) {
                    size_t off = (size_t)gyr * WD + gxv;
                    iv = Ib[off];
                    pv = Pb[off];
                }
                float oi = hi[t % 7], oq = hq[t % 7];
                sp  += pv - oq;
                sIp += iv * pv - oi * oq;
                hi[t % 7] = iv;
                hq[t % 7] = pv;
                if (t >= 6) {
                    int idx = (ya0 + t - 6) * VP + vx;
                    vp[idx]  = sp;
                    vIp[idx] = sIp;
                }
            }
        }
        __syncthreads();

        // ---------------- H1: h-sums -> a,b -> h-sums of a,b (fused) ------
        // thread = (ab-row ya in [0,70), chunk c in [0,3)); 11 out-x each
        if (tid < 210) {
            int c  = tid / 70;
            int ya = tid - c * 70;
            int gya = y0 + ya - 3;
            bool yok = (unsigned)gya < (unsigned)HD;
            int vxb = 11 * c;
            int gxa_b = x0 + vxb - 9;      // gxa = gxa_b + t
            const int rowv = ya * VP;
            const int rowh = ya * HP;
            float w0[7], w1[7], w2[7], w3[7], wa[7], wb[7];
            float s0 = 0.f, s1 = 0.f, s2 = 0.f, s3 = 0.f, sA = 0.f, sB = 0.f;
#pragma unroll
            for (int t = 0; t < 7; t++) {
                w0[t] = w1[t] = w2[t] = w3[t] = wa[t] = wb[t] = 0.f;
            }
#pragma unroll
            for (int t = 0; t < 23; t++) {
                int vx = vxb + t;
                float a0 = 0.f, a1 = 0.f, a2 = 0.f, a3 = 0.f;
                if (vx < 44) {
                    int idx = rowv + vx;
                    a0 = vI[idx]; a1 = vII[idx]; a2 = vp[idx]; a3 = vIp[idx];
                }
                int k = t % 7;
                s0 += a0 - w0[k]; s1 += a1 - w1[k];
                s2 += a2 - w2[k]; s3 += a3 - w3[k];
                w0[k] = a0; w1[k] = a1; w2[k] = a2; w3[k] = a3;
                if (t >= 6) {
                    float av = 0.f, bv = 0.f;
                    if (yok && (unsigned)(gxa_b + t) < (unsigned)WD) {
                        float mi  = s0 * INV49;
                        float mp  = s2 * INV49;
                        float var = fmaf(s1, INV49, -mi * mi);
                        float cov = fmaf(s3, INV49, -mi * mp);
                        av = cov * __fdividef(1.0f, var + EPS_GF);
                        bv = fmaf(-av, mi, mp);
                    }
                    sA += av - wa[k]; sB += bv - wb[k];
                    wa[k] = av; wb[k] = bv;
                    if (t >= 12) {
                        int ox = vxb + t - 12;
                        if (ox < 32) {
                            hsA[rowh + ox] = sA;
                            hsB[rowh + ox] = sB;
                        }
                    }
                }
            }
        }
        __syncthreads();

        // ---------------- V2: vertical 7-sum of hsA/hsB + combine + store -
        // thread = (out-x ox in [0,32), segment in [0,8)); 8 out rows each
        {
            int ox  = tid & 31;
            int seg = tid >> 5;
            int ya0 = seg * 8;
            float wa[7], wb[7];
            float sA = 0.f, sB = 0.f;
#pragma unroll
            for (int t = 0; t < 7; t++) { wa[t] = 0.f; wb[t] = 0.f; }
            float* Ob = gOut + ((size_t)bz * 3 + ch) * HW;
            const int gx = x0 + ox;
#pragma unroll
            for (int t = 0; t < 14; t++) {
                int idx = (ya0 + t) * HP + ox;
                float av = hsA[idx], bv = hsB[idx];
                int k = t % 7;
                sA += av - wa[k]; sB += bv - wb[k];
                wa[k] = av; wb[k] = bv;
                if (t >= 6) {
                    int gy = y0 + ya0 + t - 6;
                    size_t off = (size_t)gy * WD + gx;
                    float Ic = Ib[off];
                    float q = fmaf(sA * INV49, Ic, sB * INV49);
                    q = fminf(fmaxf(q, 0.0f), 1.0f);
                    Ob[off] = q;
                }
            }
        }
        __syncthreads();
    }
}

extern "C" void kernel_launch(void* const* d_in, const int* in_sizes, int n_in,
                              void* d_out, int out_size) {
    const float* I = (const float*)d_in[0];
    const float* p = (const float*)d_in[1];
    if (n_in >= 2 && in_sizes[0] > in_sizes[1]) {  // defensive: I is smaller
        const float* t = I; I = p; p = t;
    }
    float* out = (float*)d_out;

    cudaFuncSetAttribute(gf_kernel,
                         cudaFuncAttributeMaxDynamicSharedMemorySize, SMEM_BYTES);
    dim3 grid(WD / 32, HD / 64, 8);
    gf_kernel<<<grid, NT, SMEM_BYTES>>>(I, p, out);
}